// round 1
// baseline (speedup 1.0000x reference)
#include <cuda_runtime.h>
#include <cuda_fp16.h>

#define HH    8192              // strip height = B*H
#define WW    512
#define NPIX  (HH * WW)         // 4194304
#define NW    (NPIX / 32)       // 131072 words, 16 words per row
#define WPR   16                // words per row
#define HYST_BLOCKS  148
#define HYST_THREADS 256
#define HYST_TOTAL   (HYST_BLOCKS * HYST_THREADS)
#define MAX_IT 512

// ---------------- static device scratch (no allocations allowed) ----------------
__device__ __half        g_mag[NPIX];     // 8 MB  (integer magnitudes, exact in fp16)
__device__ unsigned char g_dir[NPIX];     // 4 MB  (0=h,1=v,2=diag-same,3=diag-opp)
__device__ unsigned      g_weak[NW];      // 512 KB bitmask
__device__ unsigned      g_sA[NW];        // strong ping
__device__ unsigned      g_sB[NW];        // strong pong
__device__ unsigned      g_bar;           // grid barrier counter (monotonic per launch)
__device__ int           g_changed[MAX_IT];

// ---------------- kernel A: toRGB + Sobel + channel argmax + direction ----------
__device__ __forceinline__ float pixval(const float* __restrict__ x, int Y, int X, int c) {
    int b = Y >> 9, y = Y & 511;
    float v = x[(((b * 3 + c) << 9) + y) * 512 + X];
    // ((x+1)*0.5)*255, floor, clip — explicit rn muls to forbid FMA contraction
    float t = __fmul_rn(__fmul_rn(v + 1.0f, 0.5f), 255.0f);
    t = floorf(t);
    return fminf(fmaxf(t, 0.0f), 255.0f);
}

__global__ void magdir_kernel(const float* __restrict__ x) {
    int idx = blockIdx.x * blockDim.x + threadIdx.x;
    if (idx >= NPIX) return;
    int Y = idx >> 9, X = idx & 511;
    // replicate padding on the full strip (batches touch at boundaries!)
    int ym = Y > 0 ? Y - 1 : 0;
    int yp = Y < HH - 1 ? Y + 1 : HH - 1;
    int xm = X > 0 ? X - 1 : 0;
    int xp = X < WW - 1 ? X + 1 : WW - 1;

    float bestMag = -1.0f, bgx = 0.0f, bgy = 0.0f;
#pragma unroll
    for (int c = 0; c < 3; c++) {
        float a00 = pixval(x, ym, xm, c), a01 = pixval(x, ym, X, c), a02 = pixval(x, ym, xp, c);
        float a10 = pixval(x, Y,  xm, c),                             a12 = pixval(x, Y,  xp, c);
        float a20 = pixval(x, yp, xm, c), a21 = pixval(x, yp, X, c), a22 = pixval(x, yp, xp, c);
        // all integer-valued in fp32 -> sums exact regardless of order
        float gx = (a02 + 2.0f * a12 + a22) - (a00 + 2.0f * a10 + a20);
        float gy = (a20 + 2.0f * a21 + a22) - (a00 + 2.0f * a01 + a02);
        float m = fabsf(gx) + fabsf(gy);
        if (m > bestMag) { bestMag = m; bgx = gx; bgy = gy; }   // strict > == first-max argmax
    }
    const float TG22 = (float)0.4142135623730951;
    float ax = fabsf(bgx), ay = fabsf(bgy);
    unsigned char dir;
    if (ay < __fmul_rn(TG22, ax))       dir = 0;              // ~horizontal gradient
    else if (__fmul_rn(ay, TG22) > ax)  dir = 1;              // ~vertical
    else dir = (__fmul_rn(bgx, bgy) >= 0.0f) ? 2 : 3;         // diagonal by sign agreement
    g_mag[idx] = __float2half_rn(bestMag);                    // integer <= 2040: exact
    g_dir[idx] = dir;
}

// ---------------- kernel B: NMS + thresholds -> bit-packed masks ----------------
__device__ __forceinline__ float magAt(int Y, int X) {
    // zero padding on the full strip (matches _shift)
    if ((unsigned)Y >= (unsigned)HH || (unsigned)X >= (unsigned)WW) return 0.0f;
    return __half2float(g_mag[(Y << 9) + X]);
}

__global__ void nms_kernel() {
    int idx = blockIdx.x * blockDim.x + threadIdx.x;
    int Y = idx >> 9, X = idx & 511;
    float mag = __half2float(g_mag[idx]);
    unsigned char dir = g_dir[idx];
    float n1, n2;
    if (dir == 0)      { n1 = magAt(Y,     X - 1); n2 = magAt(Y,     X + 1); }
    else if (dir == 1) { n1 = magAt(Y - 1, X);     n2 = magAt(Y + 1, X);     }
    else if (dir == 2) { n1 = magAt(Y - 1, X - 1); n2 = magAt(Y + 1, X + 1); }
    else               { n1 = magAt(Y - 1, X + 1); n2 = magAt(Y + 1, X - 1); }
    bool keep   = (mag > n1) && (mag >= n2);
    bool strong = keep && (mag > 200.0f);
    bool weak   = keep && (mag > 100.0f);
    unsigned sb = __ballot_sync(0xffffffffu, strong);
    unsigned wb = __ballot_sync(0xffffffffu, weak);
    if ((threadIdx.x & 31) == 0) {
        g_sA[idx >> 5]   = sb;
        g_weak[idx >> 5] = wb;
    }
    // reset persistent-kernel state (stream-ordered before hysteresis; makes
    // graph replays deterministic)
    if (blockIdx.x == 0) {
        for (int i = threadIdx.x; i < MAX_IT; i += blockDim.x) g_changed[i] = 0;
        if (threadIdx.x == 0) g_bar = 0u;
    }
}

// ---------------- kernel C: persistent Jacobi hysteresis + output write --------
__device__ __forceinline__ unsigned dil_row(const unsigned* src, int i, int wx) {
    unsigned s = __ldcg(&src[i]);
    unsigned l = wx        ? __ldcg(&src[i - 1]) : 0u;
    unsigned r = (wx < 15) ? __ldcg(&src[i + 1]) : 0u;
    return s | (s << 1) | (l >> 31) | (s >> 1) | (r << 31);
}

__global__ void __launch_bounds__(HYST_THREADS, 1)
hyst_kernel(float* __restrict__ out) {
    const int gtid = blockIdx.x * HYST_THREADS + threadIdx.x;
    unsigned* src = g_sA;
    unsigned* dst = g_sB;

    for (int it = 0; it < MAX_IT; ++it) {
        bool changed = false;
        for (int i = gtid; i < NW; i += HYST_TOTAL) {
            int Y = i >> 4, wx = i & 15;
            unsigned wk = g_weak[i];            // immutable this launch -> L1 ok
            unsigned s  = __ldcg(&src[i]);
            unsigned l  = wx        ? __ldcg(&src[i - 1]) : 0u;
            unsigned r  = (wx < 15) ? __ldcg(&src[i + 1]) : 0u;
            unsigned dil = s | (s << 1) | (l >> 31) | (s >> 1) | (r << 31);
            if (Y > 0)      dil |= dil_row(src, i - WPR, wx);
            if (Y < HH - 1) dil |= dil_row(src, i + WPR, wx);
            unsigned ns = wk & dil;             // == (dilate(S)&weak)|S  since S⊆weak
            dst[i] = ns;
            changed |= (ns != s);
        }
        if (changed) g_changed[it] = 1;

        // software grid barrier (all 148 blocks co-resident by construction)
        __threadfence();
        __syncthreads();
        if (threadIdx.x == 0) {
            atomicAdd(&g_bar, 1u);
            unsigned target = (unsigned)(it + 1) * HYST_BLOCKS;
            while (atomicAdd(&g_bar, 0u) < target) { }
        }
        __syncthreads();
        __threadfence();

        unsigned* t = src; src = dst; dst = t;  // result of this sweep now in src
        if (*(volatile int*)&g_changed[it] == 0) break;   // consistent across grid
    }

    // final edges -> ((e)-0.5)/0.5 in {-1,+1}, broadcast to 3 channels
    for (int i = gtid; i < NW; i += HYST_TOTAL) {
        unsigned s = __ldcg(&src[i]);
        int Y = i >> 4;
        int b = Y >> 9, y = Y & 511;
        int xb = (i & 15) << 5;
        int base = (((b * 3) << 9) + y) * 512 + xb;
#pragma unroll
        for (int c = 0; c < 3; c++) {
            float4* o = (float4*)(out + base + (c << 18));
#pragma unroll
            for (int j = 0; j < 8; j++) {
                float4 f;
                f.x = ((s >> (j * 4 + 0)) & 1u) ? 1.0f : -1.0f;
                f.y = ((s >> (j * 4 + 1)) & 1u) ? 1.0f : -1.0f;
                f.z = ((s >> (j * 4 + 2)) & 1u) ? 1.0f : -1.0f;
                f.w = ((s >> (j * 4 + 3)) & 1u) ? 1.0f : -1.0f;
                o[j] = f;
            }
        }
    }
}

// ---------------- launch ----------------
extern "C" void kernel_launch(void* const* d_in, const int* in_sizes, int n_in,
                              void* d_out, int out_size) {
    const float* x = (const float*)d_in[0];
    float* out = (float*)d_out;
    (void)in_sizes; (void)n_in; (void)out_size;

    magdir_kernel<<<NPIX / 256, 256>>>(x);
    nms_kernel<<<NPIX / 256, 256>>>();
    hyst_kernel<<<HYST_BLOCKS, HYST_THREADS>>>(out);
}

// round 3
// speedup vs baseline: 1.0648x; 1.0648x over previous
#include <cuda_runtime.h>
#include <cuda_fp16.h>

#define HH    8192              // strip height = B*H
#define WW    512
#define NPIX  (HH * WW)         // 4194304
#define NW    (NPIX / 32)       // 131072 words, 16 per row
#define WPR   16
#define MAX_IT 512
#define NB    148               // hysteresis blocks (1 per SM, co-resident)

// ---------------- static device scratch ----------------
__device__ __half        g_mag[NPIX];     // integer magnitudes <= 2040, exact in fp16
__device__ unsigned char g_dir[NPIX];
__device__ unsigned      g_weak[NW];
__device__ unsigned      g_sA[NW];        // strong mask (boundary-row exchange buffer)
__device__ unsigned      g_bar;           // monotone grid-barrier counter
__device__ int           g_changed[MAX_IT];

// ---------------- kernel A: toRGB + Sobel + channel argmax + direction ----------
__device__ __forceinline__ float tf(float v) {
    // floor(clip(((v+1)*0.5)*255)); (v+1)*0.5 is exact, so one rn-mul by 127.5 is identical
    float t = floorf(__fmul_rn(__fadd_rn(v, 1.0f), 127.5f));
    return fminf(fmaxf(t, 0.0f), 255.0f);
}

struct RowDR { float d0, d1, r0, r1; };

__device__ __forceinline__ RowDR loadrow(const float* __restrict__ x, int Y, int c,
                                         int tx, int lane) {
    int b = Y >> 9, y = Y & 511;
    const float* row = x + (((((b * 3 + c) << 9) + y)) << 9);
    int X0 = tx * 2;
    float2 v = *reinterpret_cast<const float2*>(row + X0);
    float p0 = tf(v.x), p1 = tf(v.y);
    float pl = __shfl_up_sync(0xffffffffu, p1, 1);
    float pr = __shfl_down_sync(0xffffffffu, p0, 1);
    if (lane == 0)  pl = (tx == 0)   ? p0 : tf(__ldg(row + X0 - 1));   // x replicate pad
    if (lane == 31) pr = (tx == 255) ? p1 : tf(__ldg(row + X0 + 2));
    RowDR o;
    o.d0 = p1 - pl;                  // horizontal [-1,0,1]
    o.d1 = pr - p0;
    o.r0 = pl + 2.0f * p0 + p1;      // horizontal [1,2,1]
    o.r1 = p0 + 2.0f * p1 + pr;
    return o;                        // all exact small integers in fp32
}

__device__ __forceinline__ unsigned dircode(float gx, float gy) {
    const float TG22 = (float)0.4142135623730951;
    float ax = fabsf(gx), ay = fabsf(gy);
    if (ay < __fmul_rn(TG22, ax))      return 0u;     // ~horizontal gradient
    if (__fmul_rn(ay, TG22) > ax)      return 1u;     // ~vertical
    return (__fmul_rn(gx, gy) >= 0.0f) ? 2u : 3u;     // diagonal by sign agreement
}

#define BR 16   // rows per block
__global__ void __launch_bounds__(256, 3) magdir_kernel(const float* __restrict__ x) {
    const int tx   = threadIdx.x;
    const int lane = tx & 31;
    const int X0   = tx * 2;
    const int R0   = blockIdx.x * BR;

    float D0[3][3], D1[3][3], S0[3][3], S1[3][3];  // [channel][ring slot]

#pragma unroll
    for (int c = 0; c < 3; c++) {
        RowDR a = loadrow(x, max(R0 - 1, 0), c, tx, lane);   // strip-level replicate pad
        D0[c][0] = a.d0; D1[c][0] = a.d1; S0[c][0] = a.r0; S1[c][0] = a.r1;
        RowDR b = loadrow(x, R0, c, tx, lane);
        D0[c][1] = b.d0; D1[c][1] = b.d1; S0[c][1] = b.r0; S1[c][1] = b.r1;
    }

#pragma unroll
    for (int j = 0; j < BR; j++) {
        const int Y  = R0 + j;
        const int km = j % 3, k0 = (j + 1) % 3, kp = (j + 2) % 3;
#pragma unroll
        for (int c = 0; c < 3; c++) {
            RowDR n = loadrow(x, min(Y + 1, HH - 1), c, tx, lane);
            D0[c][kp] = n.d0; D1[c][kp] = n.d1; S0[c][kp] = n.r0; S1[c][kp] = n.r1;
        }
        float bm0 = -1.0f, bx0 = 0.0f, by0 = 0.0f;
        float bm1 = -1.0f, bx1 = 0.0f, by1 = 0.0f;
#pragma unroll
        for (int c = 0; c < 3; c++) {
            float gx0 = D0[c][km] + 2.0f * D0[c][k0] + D0[c][kp];
            float gy0 = S0[c][kp] - S0[c][km];
            float m0  = fabsf(gx0) + fabsf(gy0);
            if (m0 > bm0) { bm0 = m0; bx0 = gx0; by0 = gy0; }   // first-max argmax
            float gx1 = D1[c][km] + 2.0f * D1[c][k0] + D1[c][kp];
            float gy1 = S1[c][kp] - S1[c][km];
            float m1  = fabsf(gx1) + fabsf(gy1);
            if (m1 > bm1) { bm1 = m1; bx1 = gx1; by1 = gy1; }
        }
        unsigned dc0 = dircode(bx0, by0), dc1 = dircode(bx1, by1);
        int idx = (Y << 9) + X0;
        *reinterpret_cast<__half2*>(&g_mag[idx]) = __floats2half2_rn(bm0, bm1);
        *reinterpret_cast<unsigned short*>(&g_dir[idx]) =
            (unsigned short)(dc0 | (dc1 << 8));
    }
}

// ---------------- kernel B: NMS + thresholds -> bit-packed masks ----------------
__device__ __forceinline__ float magAt(int Y, int X) {
    if ((unsigned)Y >= (unsigned)HH || (unsigned)X >= (unsigned)WW) return 0.0f; // zero pad
    return __half2float(g_mag[(Y << 9) + X]);
}

__global__ void nms_kernel() {
    int idx = blockIdx.x * blockDim.x + threadIdx.x;
    int Y = idx >> 9, X = idx & 511;
    float mag = __half2float(g_mag[idx]);
    unsigned char dir = g_dir[idx];
    float n1, n2;
    if (dir == 0)      { n1 = magAt(Y,     X - 1); n2 = magAt(Y,     X + 1); }
    else if (dir == 1) { n1 = magAt(Y - 1, X);     n2 = magAt(Y + 1, X);     }
    else if (dir == 2) { n1 = magAt(Y - 1, X - 1); n2 = magAt(Y + 1, X + 1); }
    else               { n1 = magAt(Y - 1, X + 1); n2 = magAt(Y + 1, X - 1); }
    bool keep   = (mag > n1) && (mag >= n2);
    bool strong = keep && (mag > 200.0f);
    bool weak   = keep && (mag > 100.0f);
    unsigned sb = __ballot_sync(0xffffffffu, strong);
    unsigned wb = __ballot_sync(0xffffffffu, weak);
    if ((threadIdx.x & 31) == 0) {
        g_sA[idx >> 5]   = sb;
        g_weak[idx >> 5] = wb;
    }
    if (blockIdx.x == 0) {   // reset persistent-kernel state (graph-replay determinism)
        for (int i = threadIdx.x; i < MAX_IT; i += blockDim.x) g_changed[i] = 0;
        if (threadIdx.x == 0) g_bar = 0u;
    }
}

// ---------------- kernel C: band-local hysteresis fixed point + output ----------
__global__ void __launch_bounds__(256, 1) hyst_kernel(float* __restrict__ out) {
    const int tid = threadIdx.x;
    const int b   = blockIdx.x;
    const int r0  = (b * HH) / NB;
    const int r1  = ((b + 1) * HH) / NB;
    const int nrows  = r1 - r0;          // 55 or 56
    const int nwords = nrows * WPR;
    const int g0     = r0 * WPR;

    __shared__ unsigned sS[(56 + 2) * WPR];   // row layout: [halo_top][band][halo_bot]
    __shared__ unsigned sW[56 * WPR];
    __shared__ int      sflag;                // iteration stamp (monotone)
    __shared__ int      sdone;

    for (int i = tid; i < nwords; i += 256) sW[i]       = g_weak[g0 + i];
    for (int i = tid; i < nwords; i += 256) sS[WPR + i] = g_sA[g0 + i];

    for (int round = 0; round < MAX_IT; ++round) {
        // refresh halo rows from neighbors' boundary-row writes
        if (tid < WPR)
            sS[tid] = (r0 > 0) ? __ldcg(&g_sA[(r0 - 1) * WPR + tid]) : 0u;
        else if (tid < 2 * WPR) {
            int wx = tid - WPR;
            sS[(nrows + 1) * WPR + wx] = (r1 < HH) ? __ldcg(&g_sA[r1 * WPR + wx]) : 0u;
        }
        if (tid == 0) sflag = -1;
        __syncthreads();

        // local fixed point (in-place; monotone growth -> least fixed point)
        int it = 0;
        for (; it < 4096; ++it) {
            bool ch = false;
            for (int i = tid; i < nwords; i += 256) {
                unsigned w = sW[i];
                unsigned s = sS[WPR + i];
                if (s == w) continue;                 // saturated (covers w==0)
                int wx = i & 15;
                unsigned d = 0;
#pragma unroll
                for (int rr = 0; rr < 3; ++rr) {
                    int j = i + rr * WPR;             // rows y-1, y, y+1 in sS
                    unsigned c = sS[j];
                    unsigned l = wx        ? sS[j - 1] : 0u;   // x zero-pad
                    unsigned r = (wx < 15) ? sS[j + 1] : 0u;
                    d |= c | (c << 1) | (l >> 31) | (c >> 1) | (r << 31);
                }
                unsigned ns = w & d;                  // == (dilate(S)&weak)|S since S⊆weak
                if (ns != s) { sS[WPR + i] = ns; ch = true; }
            }
            if (ch) sflag = it;                       // racing same-value stores: fine
            __syncthreads();
            if (sflag < it) break;                    // monotone stamp: race-free
        }
        bool bandChanged = (sflag >= 0);

        // publish boundary rows for neighbor halos
        if (tid < WPR)
            g_sA[r0 * WPR + tid] = sS[WPR + tid];
        else if (tid < 2 * WPR) {
            int wx = tid - WPR;
            g_sA[(r1 - 1) * WPR + wx] = sS[WPR + (nrows - 1) * WPR + wx];
        }
        if (tid == 0 && bandChanged) g_changed[round] = 1;

        // grid barrier (NB blocks co-resident)
        __threadfence();
        __syncthreads();
        if (tid == 0) {
            atomicAdd(&g_bar, 1u);
            unsigned target = (unsigned)(round + 1) * NB;
            while (atomicAdd(&g_bar, 0u) < target) { }
            sdone = (*(volatile int*)&g_changed[round] == 0);
        }
        __syncthreads();
        if (sdone) break;
    }

    // final edges -> {-1,+1}, broadcast to 3 channels (write from smem band)
    for (int i = tid; i < nwords; i += 256) {
        unsigned s = sS[WPR + i];
        int Y  = r0 + (i >> 4);
        int bb = Y >> 9, y = Y & 511;
        int xb = (i & 15) << 5;
        int base = (((bb * 3) << 9) + y) * 512 + xb;
#pragma unroll
        for (int c = 0; c < 3; c++) {
            float4* o = (float4*)(out + base + (c << 18));
#pragma unroll
            for (int j = 0; j < 8; j++) {
                float4 f;
                f.x = ((s >> (j * 4 + 0)) & 1u) ? 1.0f : -1.0f;
                f.y = ((s >> (j * 4 + 1)) & 1u) ? 1.0f : -1.0f;
                f.z = ((s >> (j * 4 + 2)) & 1u) ? 1.0f : -1.0f;
                f.w = ((s >> (j * 4 + 3)) & 1u) ? 1.0f : -1.0f;
                o[j] = f;
            }
        }
    }
}

// ---------------- launch ----------------
extern "C" void kernel_launch(void* const* d_in, const int* in_sizes, int n_in,
                              void* d_out, int out_size) {
    const float* x = (const float*)d_in[0];
    float* out = (float*)d_out;
    (void)in_sizes; (void)n_in; (void)out_size;

    magdir_kernel<<<HH / BR, 256>>>(x);
    nms_kernel<<<NPIX / 256, 256>>>();
    hyst_kernel<<<NB, 256>>>(out);
}

// round 4
// speedup vs baseline: 1.7925x; 1.6835x over previous
#include <cuda_runtime.h>
#include <cuda_fp16.h>

#define HH    8192              // strip height = B*H
#define WW    512
#define NPIX  (HH * WW)
#define NW    (NPIX / 32)       // 131072 words, 16 per row
#define WPR   16
#define MAX_IT 512
#define NB    148               // hysteresis blocks (1 per SM, co-resident)
#define TR    8                 // NMS output rows per block in fused kernel

// ---------------- static device scratch ----------------
__device__ unsigned g_weak[NW];
__device__ unsigned g_sA[NW];         // strong mask (boundary-row exchange buffer)
__device__ unsigned g_bar;            // monotone grid-barrier counter
__device__ int      g_changed[MAX_IT];

// ---------------- fused kernel: toRGB+Sobel+argmax+NMS+threshold+pack ----------
__device__ __forceinline__ float tf(float v) {
    // floor(clip(((v+1)*0.5)*255)); (v+1)*0.5 exact -> one rn-mul by 127.5 identical
    float t = floorf(__fmul_rn(__fadd_rn(v, 1.0f), 127.5f));
    return fminf(fmaxf(t, 0.0f), 255.0f);
}

__device__ __forceinline__ unsigned dircode(float gx, float gy) {
    const float TG22 = (float)0.4142135623730951;
    float ax = fabsf(gx), ay = fabsf(gy);
    if (ay < __fmul_rn(TG22, ax))      return 0u;     // ~horizontal gradient
    if (__fmul_rn(ay, TG22) > ax)      return 1u;     // ~vertical
    return (__fmul_rn(gx, gy) >= 0.0f) ? 2u : 3u;     // diagonal by sign agreement
}

__global__ void __launch_bounds__(512, 2) magnms_kernel(const float* __restrict__ x) {
    __shared__ __half sPix[3][TR + 4][WW];   // transformed pixels (ints <=255, exact)
    __shared__ __half sMag[TR + 2][WW];      // magnitudes (ints <=2040, exact)

    const int tx = threadIdx.x;              // column 0..511
    const int R0 = blockIdx.x * TR;

    // ---- phase 1: cooperative float4 load + transform once + store half ----
    // 36 row-channels of 128 float4 each = 4608 float4 loads per block
#pragma unroll
    for (int k = 0; k < 9; k++) {
        int i = tx + k * 512;
        int row_ch = i >> 7;                 // 0..35
        int x4 = (i & 127) << 2;
        int c  = row_ch / 12;
        int rr = row_ch - c * 12;
        int Y  = min(max(R0 - 2 + rr, 0), HH - 1);   // strip-level replicate pad
        int b = Y >> 9, y = Y & 511;
        float4 v = *reinterpret_cast<const float4*>(
            x + ((((size_t)(b * 3 + c) << 9) + y) << 9) + x4);
        __half2 h0 = __floats2half2_rn(tf(v.x), tf(v.y));
        __half2 h1 = __floats2half2_rn(tf(v.z), tf(v.w));
        *reinterpret_cast<__half2*>(&sPix[c][rr][x4])     = h0;
        *reinterpret_cast<__half2*>(&sPix[c][rr][x4 + 2]) = h1;
    }
    __syncthreads();

    // ---- phase 2: separable Sobel with register ring, write mag rows ----
    const int xl = max(tx - 1, 0), xr = min(tx + 1, WW - 1);  // x replicate pad
    float d[3][3], r[3][3];                  // [channel][ring slot]
#pragma unroll
    for (int pr = 0; pr < 2; pr++) {
#pragma unroll
        for (int c = 0; c < 3; c++) {
            float pl = __half2float(sPix[c][pr][xl]);
            float p0 = __half2float(sPix[c][pr][tx]);
            float prr = __half2float(sPix[c][pr][xr]);
            d[c][pr] = prr - pl;
            r[c][pr] = pl + 2.0f * p0 + prr;
        }
    }
    float    mj[TR];
    unsigned dirpack = 0;
#pragma unroll
    for (int m = 0; m < TR + 2; m++) {       // mag row m, abs Y = R0-1+m
        const int pr = m + 2;
        const int kc = pr % 3, km = m % 3, k0 = (m + 1) % 3;
#pragma unroll
        for (int c = 0; c < 3; c++) {
            float pl = __half2float(sPix[c][pr][xl]);
            float p0 = __half2float(sPix[c][pr][tx]);
            float prr = __half2float(sPix[c][pr][xr]);
            d[c][kc] = prr - pl;
            r[c][kc] = pl + 2.0f * p0 + prr;
        }
        float bm = -1.0f, bx = 0.0f, by = 0.0f;
#pragma unroll
        for (int c = 0; c < 3; c++) {
            float gx = d[c][km] + 2.0f * d[c][k0] + d[c][kc];
            float gy = r[c][kc] - r[c][km];           // all exact small ints
            float mg = fabsf(gx) + fabsf(gy);
            if (mg > bm) { bm = mg; bx = gx; by = gy; }   // first-max argmax
        }
        int absY = R0 - 1 + m;
        bool inR = (absY >= 0) && (absY < HH);
        sMag[m][tx] = __float2half_rn(inR ? bm : 0.0f);   // zero pad for NMS shifts
        if (m >= 1 && m <= TR) {
            mj[m - 1] = bm;
            dirpack |= dircode(bx, by) << (2 * (m - 1));
        }
    }
    __syncthreads();

    // ---- phase 3: NMS + thresholds + ballot pack ----
    const int lane = tx & 31;
    const int widx0 = (R0 << 4) + (tx >> 5);
    const bool hasL = (tx > 0), hasR = (tx < WW - 1);
#pragma unroll
    for (int j = 0; j < TR; j++) {
        const int m = j + 1;
        float mag = mj[j];
        unsigned dir = (dirpack >> (2 * j)) & 3u;
        float n1, n2;
        if (dir == 0)      { n1 = hasL ? __half2float(sMag[m][tx - 1]) : 0.0f;
                             n2 = hasR ? __half2float(sMag[m][tx + 1]) : 0.0f; }
        else if (dir == 1) { n1 = __half2float(sMag[m - 1][tx]);
                             n2 = __half2float(sMag[m + 1][tx]); }
        else if (dir == 2) { n1 = hasL ? __half2float(sMag[m - 1][tx - 1]) : 0.0f;
                             n2 = hasR ? __half2float(sMag[m + 1][tx + 1]) : 0.0f; }
        else               { n1 = hasR ? __half2float(sMag[m - 1][tx + 1]) : 0.0f;
                             n2 = hasL ? __half2float(sMag[m + 1][tx - 1]) : 0.0f; }
        bool keep   = (mag > n1) && (mag >= n2);
        bool strong = keep && (mag > 200.0f);
        bool weak   = keep && (mag > 100.0f);
        unsigned sb = __ballot_sync(0xffffffffu, strong);
        unsigned wb = __ballot_sync(0xffffffffu, weak);
        if (lane == 0) {
            g_sA[widx0 + j * WPR]   = sb;
            g_weak[widx0 + j * WPR] = wb;
        }
    }

    // reset persistent-kernel state (stream-ordered before hyst; replay-safe)
    if (blockIdx.x == 0) {
        for (int i = tx; i < MAX_IT; i += 512) g_changed[i] = 0;
        if (tx == 0) g_bar = 0u;
    }
}

// ---------------- hysteresis: band-local fixed point + output ----------------
__device__ __forceinline__ unsigned runfill(unsigned w, unsigned s) {
    // horizontal transitive closure of seeds s within 1-runs of w (s subset of w)
    unsigned up = w & ~(w + s);
    unsigned dn = __brev(__brev(w) & ~(__brev(w) + __brev(s)));
    return s | up | dn;
}

__global__ void __launch_bounds__(256, 1) hyst_kernel(float* __restrict__ out) {
    const int tid = threadIdx.x;
    const int b   = blockIdx.x;
    const int r0  = (b * HH) / NB;
    const int r1  = ((b + 1) * HH) / NB;
    const int nrows  = r1 - r0;          // 55 or 56
    const int nwords = nrows * WPR;
    const int g0     = r0 * WPR;

    __shared__ unsigned sS[(56 + 2) * WPR];   // [halo_top][band][halo_bot]
    __shared__ int      sflag, sdone;

    unsigned wreg[4];                         // weak words cached in registers
#pragma unroll
    for (int k = 0; k < 4; k++) {
        int i = tid + k * 256;
        wreg[k] = (i < nwords) ? g_weak[g0 + i] : 0u;
        if (i < nwords) sS[WPR + i] = g_sA[g0 + i];
    }

    for (int round = 0; round < MAX_IT; ++round) {
        if (tid < WPR)
            sS[tid] = (r0 > 0) ? __ldcg(&g_sA[(r0 - 1) * WPR + tid]) : 0u;
        else if (tid < 2 * WPR) {
            int wx = tid - WPR;
            sS[(nrows + 1) * WPR + wx] = (r1 < HH) ? __ldcg(&g_sA[r1 * WPR + wx]) : 0u;
        }
        if (tid == 0) sflag = -1;
        __syncthreads();

        // local fixed point (in-place; monotone -> least fixed point)
        for (int it = 0; it < 4096; ++it) {
            bool ch = false;
#pragma unroll
            for (int k = 0; k < 4; k++) {
                int i = tid + k * 256;
                unsigned w = wreg[k];
                if (i >= nwords) continue;
                unsigned s = sS[WPR + i];
                if (s == w) continue;              // saturated (covers w==0)
                int wx = i & 15;
                unsigned dil = 0;
#pragma unroll
                for (int rr = 0; rr < 3; ++rr) {
                    int j = i + rr * WPR;          // rows y-1,y,y+1 in sS
                    unsigned c = sS[j];
                    unsigned l = wx        ? sS[j - 1] : 0u;   // x zero-pad
                    unsigned r = (wx < 15) ? sS[j + 1] : 0u;
                    dil |= c | (c << 1) | (l >> 31) | (c >> 1) | (r << 31);
                }
                unsigned ns = runfill(w, w & dil); // == (dilate&weak)|S since S⊆weak
                if (ns != s) { sS[WPR + i] = ns; ch = true; }
            }
            if (ch) sflag = it;                    // monotone stamp: race-free
            __syncthreads();
            if (sflag < it) break;
        }
        bool bandChanged = (sflag >= 0);

        // publish boundary rows for neighbor halos
        if (tid < WPR)
            g_sA[r0 * WPR + tid] = sS[WPR + tid];
        else if (tid < 2 * WPR) {
            int wx = tid - WPR;
            g_sA[(r1 - 1) * WPR + wx] = sS[WPR + (nrows - 1) * WPR + wx];
        }
        if (tid == 0 && bandChanged) g_changed[round] = 1;

        // grid barrier (NB co-resident blocks)
        __threadfence();
        __syncthreads();
        if (tid == 0) {
            atomicAdd(&g_bar, 1u);
            unsigned target = (unsigned)(round + 1) * NB;
            while (atomicAdd(&g_bar, 0u) < target) { }
            sdone = (*(volatile int*)&g_changed[round] == 0);
        }
        __syncthreads();
        if (sdone) break;
    }

    // final edges -> {-1,+1}, broadcast to 3 channels
    for (int i = tid; i < nwords; i += 256) {
        unsigned s = sS[WPR + i];
        int Y  = r0 + (i >> 4);
        int bb = Y >> 9, y = Y & 511;
        int xb = (i & 15) << 5;
        int base = (((bb * 3) << 9) + y) * 512 + xb;
#pragma unroll
        for (int c = 0; c < 3; c++) {
            float4* o = (float4*)(out + base + (c << 18));
#pragma unroll
            for (int j = 0; j < 8; j++) {
                float4 f;
                f.x = ((s >> (j * 4 + 0)) & 1u) ? 1.0f : -1.0f;
                f.y = ((s >> (j * 4 + 1)) & 1u) ? 1.0f : -1.0f;
                f.z = ((s >> (j * 4 + 2)) & 1u) ? 1.0f : -1.0f;
                f.w = ((s >> (j * 4 + 3)) & 1u) ? 1.0f : -1.0f;
                o[j] = f;
            }
        }
    }
}

// ---------------- launch ----------------
extern "C" void kernel_launch(void* const* d_in, const int* in_sizes, int n_in,
                              void* d_out, int out_size) {
    const float* x = (const float*)d_in[0];
    float* out = (float*)d_out;
    (void)in_sizes; (void)n_in; (void)out_size;

    magnms_kernel<<<HH / TR, 512>>>(x);
    hyst_kernel<<<NB, 256>>>(out);
}